// round 16
// baseline (speedup 1.0000x reference)
#include <cuda_runtime.h>
#include <cuda_bf16.h>
#include <math.h>
#include <stdint.h>

#define N_NODES 200000
#define N_EDGES 1250000
#define G 128
#define CAP 64
#define NT 782             // ceil(N_NODES / 256)
#define NPAD (NT * 256)    // 200192 padded rows

// ---- dynamic smem byte offsets (k_gemm) ----
#define SM_W1H  0
#define SM_W1L  9216
#define SM_W2H  18432
#define SM_W2L  27648
#define SM_AH   36864      // 256 rows x 144 B
#define SM_AL   73728
#define SM_B1   110592
#define SM_B2   110848
#define SM_TOTAL 111104
#define ROWB 144           // padded row stride in bytes (72 halves)

// ---------------- device scratch (zero-initialized at load) ----------------
__device__ int      g_cnt[N_NODES];       // degree cursor; zero at call start
__device__ int      g_esrc[N_NODES * CAP];
__device__ uint32_t g_zh[NPAD * 32];      // z rows, bf16x2 hi words
__device__ uint32_t g_zl[NPAD * 32];      // z rows, bf16x2 lo (residual) words
__device__ float    g_h1[N_NODES * 64];
__device__ float    g_h2[N_NODES * 64];
__device__ float    g_pool[G * 2 * 64];
__device__ int      g_gb[G + 1];

// ---------------- helpers ----------------
__device__ __forceinline__ uint32_t smem_u32(const void* p) {
    uint32_t a;
    asm("{ .reg .u64 t; cvta.to.shared.u64 t, %1; cvt.u32.u64 %0, t; }" : "=r"(a) : "l"(p));
    return a;
}
__device__ __forceinline__ void ldm_x4(uint32_t addr, uint32_t r[4]) {
    asm volatile("ldmatrix.sync.aligned.m8n8.x4.shared.b16 {%0,%1,%2,%3}, [%4];"
                 : "=r"(r[0]), "=r"(r[1]), "=r"(r[2]), "=r"(r[3]) : "r"(addr));
}
__device__ __forceinline__ void ldm_x4t(uint32_t addr, uint32_t r[4]) {
    asm volatile("ldmatrix.sync.aligned.m8n8.x4.trans.shared.b16 {%0,%1,%2,%3}, [%4];"
                 : "=r"(r[0]), "=r"(r[1]), "=r"(r[2]), "=r"(r[3]) : "r"(addr));
}
__device__ __forceinline__ void mma_bf16(float* c, const uint32_t a[4],
                                         uint32_t b0, uint32_t b1) {
    asm volatile("mma.sync.aligned.m16n8k16.row.col.f32.bf16.bf16.f32 "
                 "{%0,%1,%2,%3}, {%4,%5,%6,%7}, {%8,%9}, {%0,%1,%2,%3};"
                 : "+f"(c[0]), "+f"(c[1]), "+f"(c[2]), "+f"(c[3])
                 : "r"(a[0]), "r"(a[1]), "r"(a[2]), "r"(a[3]), "r"(b0), "r"(b1));
}
__device__ __forceinline__ void split_bf16(float v, uint16_t& hi, uint16_t& lo) {
    __nv_bfloat16 h = __float2bfloat16(v);
    float r = v - __bfloat162float(h);
    __nv_bfloat16 l = __float2bfloat16(r);
    hi = __bfloat16_as_ushort(h);
    lo = __bfloat16_as_ushort(l);
}
// packed hi/lo split of a pair: hp = {lo16=bf16(v0), hi16=bf16(v1)}, lp = residuals
__device__ __forceinline__ void split2(float v0, float v1, uint32_t& hp, uint32_t& lp) {
    asm("cvt.rn.bf16x2.f32 %0, %1, %2;" : "=r"(hp) : "f"(v1), "f"(v0));
    float h0 = __uint_as_float(hp << 16);
    float h1 = __uint_as_float(hp & 0xffff0000u);
    float r0 = v0 - h0, r1 = v1 - h1;
    asm("cvt.rn.bf16x2.f32 %0, %1, %2;" : "=r"(lp) : "f"(r1), "f"(r0));
}

// one 64x64 GEMM layer: acc[8][4] = A(16x64, this warp's rows) @ W(64x64)
// 3-term hi/lo: Ah*Wh + Ah*Wl + Al*Wh.
// W fragments via x4.trans: lanes 0-15 -> n-block jp*2, lanes 16-31 -> jp*2+1.
__device__ __forceinline__ void layer64(uint32_t aHi, uint32_t aLo,
                                        uint32_t wHi, uint32_t wLo,
                                        int lane, float acc[8][4]) {
    #pragma unroll
    for (int j = 0; j < 8; j++)
        #pragma unroll
        for (int q = 0; q < 4; q++) acc[j][q] = 0.f;

    uint32_t aOff = (uint32_t)(((lane & 7) + ((lane >> 3) & 1) * 8) * ROWB
                               + ((lane >> 4) * 8) * 2);
    int jhalf = (lane >> 4) & 1;
    #pragma unroll
    for (int kk = 0; kk < 4; kk++) {
        uint32_t ah[4], al[4];
        uint32_t ao = aOff + kk * 32;          // +16 halves per k-step
        ldm_x4(aHi + ao, ah);
        ldm_x4(aLo + ao, al);
        uint32_t brow = kk * 16 + (lane & 15);
        #pragma unroll
        for (int jp = 0; jp < 4; jp++) {
            int jj = jp * 2 + jhalf;
            uint32_t bo = (brow * 72 + jj * 8) * 2;
            uint32_t bh[4], bl[4];
            ldm_x4t(wHi + bo, bh);
            ldm_x4t(wLo + bo, bl);
            mma_bf16(acc[jp * 2],     ah, bh[0], bh[1]);
            mma_bf16(acc[jp * 2],     ah, bl[0], bl[1]);
            mma_bf16(acc[jp * 2],     al, bh[0], bh[1]);
            mma_bf16(acc[jp * 2 + 1], ah, bh[2], bh[3]);
            mma_bf16(acc[jp * 2 + 1], ah, bl[2], bl[3]);
            mma_bf16(acc[jp * 2 + 1], al, bh[2], bh[3]);
        }
    }
}

// ---------------- scatter: bucket edges by dst (4 edges/thread) + gb in last block ----------------
__global__ void k_scatter(const int* __restrict__ e32, const int* __restrict__ b32, int nQB) {
    __shared__ int s_is64;
    if (threadIdx.x == 0) {
        int all0 = 1;
        #pragma unroll 1
        for (int i = 0; i < 64; i++)
            if (e32[2 * i + 1] != 0) { all0 = 0; break; }
        s_is64 = all0;
    }
    __syncthreads();
    if ((int)blockIdx.x == nQB) {
        // graph boundary binary search (batch is sorted)
        int g = threadIdx.x;
        if (g > G) return;
        int lo = 0, hi = N_NODES;
        const long long* b64 = (const long long*)b32;
        while (lo < hi) {
            int mid = (lo + hi) >> 1;
            int bv = s_is64 ? (int)b64[mid] : b32[mid];
            if (bv < g) lo = mid + 1; else hi = mid;
        }
        g_gb[g] = lo;
        return;
    }
    int q = blockIdx.x * blockDim.x + threadIdx.x;
    int e0 = q * 4;
    if (e0 >= N_EDGES) return;
    int src[4], dst[4];
    if (s_is64) {
        const longlong2* ps = (const longlong2*)e32;
        const longlong2* pd = (const longlong2*)((const long long*)e32 + N_EDGES);
        longlong2 s01 = __ldg(ps + (e0 >> 1));
        longlong2 s23 = __ldg(ps + (e0 >> 1) + 1);
        longlong2 d01 = __ldg(pd + (e0 >> 1));
        longlong2 d23 = __ldg(pd + (e0 >> 1) + 1);
        src[0] = (int)s01.x; src[1] = (int)s01.y; src[2] = (int)s23.x; src[3] = (int)s23.y;
        dst[0] = (int)d01.x; dst[1] = (int)d01.y; dst[2] = (int)d23.x; dst[3] = (int)d23.y;
    } else {
        int4 s = __ldg((const int4*)e32 + q);
        int4 d = __ldg((const int4*)(e32 + N_EDGES) + q);
        src[0] = s.x; src[1] = s.y; src[2] = s.z; src[3] = s.w;
        dst[0] = d.x; dst[1] = d.y; dst[2] = d.z; dst[3] = d.w;
    }
    #pragma unroll
    for (int j = 0; j < 4; j++) {
        int pos = atomicAdd(&g_cnt[dst[j]], 1);
        if (pos < CAP) g_esrc[((size_t)dst[j] << 6) + pos] = src[j];
    }
}

// ---------------- gather: z = x_i + sum_j x_j, bf16 hi/lo split -> global ----------------
// warp-per-node, no smem -> high occupancy; 8-wide predicated load batches.
__global__ void __launch_bounds__(256) k_gather(const float* __restrict__ xin) {
    int gw = (int)((blockIdx.x * 256 + threadIdx.x) >> 5);
    int lane = threadIdx.x & 31;
    if (gw >= N_NODES) return;
    const float2* __restrict__ x2 = (const float2*)xin;

    int deg = min(g_cnt[gw], CAP);
    const int* es = g_esrc + ((size_t)gw << 6);
    int eA = (lane < deg)      ? __ldg(es + lane)      : 0;
    int eB = (lane + 32 < deg) ? __ldg(es + lane + 32) : 0;
    float2 a = x2[(size_t)gw * 32 + lane];

    #pragma unroll 1
    for (int e = 0; e < deg; e += 8) {
        float2 v[8];
        #pragma unroll
        for (int k = 0; k < 8; k++) {
            int idx = e + k;
            int s = __shfl_sync(0xffffffffu, (idx < 32) ? eA : eB, idx & 31);
            v[k] = __ldg(&x2[(size_t)((idx < deg) ? s : 0) * 32 + lane]);
        }
        float sx0 = 0.f, sy0 = 0.f, sx1 = 0.f, sy1 = 0.f;
        #pragma unroll
        for (int k = 0; k < 8; k += 2) {
            if (e + k < deg)     { sx0 += v[k].x;     sy0 += v[k].y; }
            if (e + k + 1 < deg) { sx1 += v[k + 1].x; sy1 += v[k + 1].y; }
        }
        a.x += sx0 + sx1;
        a.y += sy0 + sy1;
    }

    uint32_t hp, lp;
    split2(a.x, a.y, hp, lp);
    g_zh[(size_t)gw * 32 + lane] = hp;
    g_zl[(size_t)gw * 32 + lane] = lp;
}

// ---------------- GEMM: h = [relu]( relu(z@w1+b1) @ w2 + b2 ), z from g_zh/g_zl ----------------
template <bool RELU_OUT>
__global__ void __launch_bounds__(512, 2)
k_gemm(float* __restrict__ hout,
       const float* __restrict__ w1, const float* __restrict__ b1,
       const float* __restrict__ w2, const float* __restrict__ b2) {
    extern __shared__ char smc[];
    uint32_t sb = smem_u32(smc);
    int t = threadIdx.x, w = t >> 5, lane = t & 31;

    // ---- weights: split hi/lo into padded [k][n] tiles ----
    for (int idx = t; idx < 4096; idx += 512) {
        int k = idx >> 6, n = idx & 63;
        uint32_t off = (uint32_t)(k * 72 + n) * 2;
        uint16_t hi, lo;
        split_bf16(w1[idx], hi, lo);
        *(uint16_t*)(smc + SM_W1H + off) = hi;
        *(uint16_t*)(smc + SM_W1L + off) = lo;
        split_bf16(w2[idx], hi, lo);
        *(uint16_t*)(smc + SM_W2H + off) = hi;
        *(uint16_t*)(smc + SM_W2L + off) = lo;
    }
    if (t < 64) {
        ((float*)(smc + SM_B1))[t] = b1[t];
        ((float*)(smc + SM_B2))[t] = b2[t];
    }

    // ---- stream z tile (256 rows) global -> padded smem, coalesced uint4 ----
    int base = (int)blockIdx.x << 8;
    {
        const uint4* zh4 = (const uint4*)(g_zh + (size_t)base * 32);
        const uint4* zl4 = (const uint4*)(g_zl + (size_t)base * 32);
        #pragma unroll
        for (int idx = t; idx < 2048; idx += 512) {
            int row = idx >> 3, q = idx & 7;
            *(uint4*)(smc + SM_AH + row * ROWB + q * 16) = __ldg(zh4 + idx);
            *(uint4*)(smc + SM_AL + row * ROWB + q * 16) = __ldg(zl4 + idx);
        }
    }
    __syncthreads();

    const float* b1s = (const float*)(smc + SM_B1);
    const float* b2s = (const float*)(smc + SM_B2);
    const uint32_t aHiW = sb + SM_AH + (uint32_t)(w * 16 * ROWB);
    const uint32_t aLoW = sb + SM_AL + (uint32_t)(w * 16 * ROWB);
    char* aHiB = smc + SM_AH + w * 16 * ROWB;
    char* aLoB = smc + SM_AL + w * 16 * ROWB;

    int r0 = lane >> 2;
    int cq = (lane & 3) * 2;

    // ---- layer 1 ----
    float acc[8][4];
    layer64(aHiW, aLoW, sb + SM_W1H, sb + SM_W1L, lane, acc);

    // epilogue 1: bias + relu, split back into own A rows (warp-private)
    #pragma unroll
    for (int j = 0; j < 8; j++) {
        int cb = j * 8 + cq;
        float v0 = fmaxf(acc[j][0] + b1s[cb],     0.f);
        float v1 = fmaxf(acc[j][1] + b1s[cb + 1], 0.f);
        float v2 = fmaxf(acc[j][2] + b1s[cb],     0.f);
        float v3 = fmaxf(acc[j][3] + b1s[cb + 1], 0.f);
        uint32_t hp0, lp0, hp1, lp1;
        split2(v0, v1, hp0, lp0);
        split2(v2, v3, hp1, lp1);
        *(uint32_t*)(aHiB + r0 * ROWB + cb * 2)       = hp0;
        *(uint32_t*)(aLoB + r0 * ROWB + cb * 2)       = lp0;
        *(uint32_t*)(aHiB + (r0 + 8) * ROWB + cb * 2) = hp1;
        *(uint32_t*)(aLoB + (r0 + 8) * ROWB + cb * 2) = lp1;
    }
    __syncwarp();

    // ---- layer 2 ----
    layer64(aHiW, aLoW, sb + SM_W2H, sb + SM_W2L, lane, acc);

    // epilogue 2: bias (+relu) -> gmem f32 (guarded for padded tail rows)
    int n0 = base + w * 16 + r0;
    int n1 = n0 + 8;
    #pragma unroll
    for (int j = 0; j < 8; j++) {
        int cb = j * 8 + cq;
        float v0 = acc[j][0] + b2s[cb];
        float v1 = acc[j][1] + b2s[cb + 1];
        float v2 = acc[j][2] + b2s[cb];
        float v3 = acc[j][3] + b2s[cb + 1];
        if (RELU_OUT) {
            v0 = fmaxf(v0, 0.f); v1 = fmaxf(v1, 0.f);
            v2 = fmaxf(v2, 0.f); v3 = fmaxf(v3, 0.f);
        }
        if (n0 < N_NODES) *(float2*)(hout + (size_t)n0 * 64 + cb) = make_float2(v0, v1);
        if (n1 < N_NODES) *(float2*)(hout + (size_t)n1 * 64 + cb) = make_float2(v2, v3);
    }
}

// ---------------- pooling (+ re-zero g_cnt) ----------------
__global__ void __launch_bounds__(512) k_pool(const float* __restrict__ h) {
    for (int i = blockIdx.x * blockDim.x + threadIdx.x; i < N_NODES;
         i += gridDim.x * blockDim.x)
        g_cnt[i] = 0;

    __shared__ float ssum[8][64], smax[8][64];
    int g = blockIdx.x, t = threadIdx.x;
    int col = t & 63, ch = t >> 6;
    int beg = g_gb[g], end = g_gb[g + 1];
    float s = 0.f, m = -INFINITY;
    for (int i = beg + ch; i < end; i += 8) {
        float v = h[i * 64 + col];
        s += v; m = fmaxf(m, v);
    }
    ssum[ch][col] = s; smax[ch][col] = m;
    __syncthreads();
    if (t < 64) {
        float S = 0.f, M = -INFINITY;
        #pragma unroll
        for (int c = 0; c < 8; c++) { S += ssum[c][t]; M = fmaxf(M, smax[c][t]); }
        g_pool[g * 128 + t]      = S;
        g_pool[g * 128 + 64 + t] = M;
    }
}

// ---------------- head MLP ----------------
__device__ __forceinline__ float silu(float x) { return x / (1.f + expf(-x)); }

__global__ void __launch_bounds__(128) k_head(float* __restrict__ out,
        const float* __restrict__ w0, const float* __restrict__ b0,
        const float* __restrict__ w1, const float* __restrict__ b1,
        const float* __restrict__ w2, const float* __restrict__ b2,
        const float* __restrict__ w3, const float* __restrict__ b3,
        const float* __restrict__ w4, const float* __restrict__ b4) {
    __shared__ float bufA[128], bufB[128];
    int g = blockIdx.x, t = threadIdx.x;
    bufA[t] = g_pool[g * 128 + t];
    __syncthreads();
    {
        float a = b0[t];
        #pragma unroll 8
        for (int k = 0; k < 128; k++) a = fmaf(bufA[k], w0[k * 128 + t], a);
        bufB[t] = silu(a);
    }
    __syncthreads();
    if (t < 64) {
        float a = b1[t];
        #pragma unroll 8
        for (int k = 0; k < 128; k++) a = fmaf(bufB[k], w1[k * 64 + t], a);
        bufA[t] = silu(a);
    }
    __syncthreads();
    if (t < 32) {
        float a = b2[t];
        #pragma unroll 8
        for (int k = 0; k < 64; k++) a = fmaf(bufA[k], w2[k * 32 + t], a);
        bufB[t] = silu(a);
    }
    __syncthreads();
    if (t < 16) {
        float a = b3[t];
        #pragma unroll
        for (int k = 0; k < 32; k++) a = fmaf(bufB[k], w3[k * 16 + t], a);
        bufA[t] = silu(a);
    }
    __syncthreads();
    if (t == 0) {
        float a = b4[0];
        #pragma unroll
        for (int k = 0; k < 16; k++) a = fmaf(bufA[k], w4[k], a);
        out[g] = a;
    }
}

// ---------------- launch ----------------
extern "C" void kernel_launch(void* const* d_in, const int* in_sizes, int n_in,
                              void* d_out, int out_size) {
    const float* x     = (const float*)d_in[0];
    const int*   eidx  = (const int*)d_in[1];
    const int*   batch = (const int*)d_in[2];
    const float* c1w1 = (const float*)d_in[3];
    const float* c1b1 = (const float*)d_in[4];
    const float* c1w2 = (const float*)d_in[5];
    const float* c1b2 = (const float*)d_in[6];
    const float* c2w1 = (const float*)d_in[7];
    const float* c2b1 = (const float*)d_in[8];
    const float* c2w2 = (const float*)d_in[9];
    const float* c2b2 = (const float*)d_in[10];
    const float* hw0 = (const float*)d_in[11];
    const float* hb0 = (const float*)d_in[12];
    const float* hw1 = (const float*)d_in[13];
    const float* hb1 = (const float*)d_in[14];
    const float* hw2 = (const float*)d_in[15];
    const float* hb2 = (const float*)d_in[16];
    const float* hw3 = (const float*)d_in[17];
    const float* hb3 = (const float*)d_in[18];
    const float* hw4 = (const float*)d_in[19];
    const float* hb4 = (const float*)d_in[20];
    float* out = (float*)d_out;

    void *p1, *p2;
    cudaGetSymbolAddress(&p1, g_h1);
    cudaGetSymbolAddress(&p2, g_h2);
    float* h1 = (float*)p1;
    float* h2 = (float*)p2;

    static int attrDone = 0;
    if (!attrDone) {
        cudaFuncSetAttribute(k_gemm<true>,  cudaFuncAttributeMaxDynamicSharedMemorySize, SM_TOTAL);
        cudaFuncSetAttribute(k_gemm<false>, cudaFuncAttributeMaxDynamicSharedMemorySize, SM_TOTAL);
        attrDone = 1;
    }

    const int QB = (N_EDGES / 4 + 255) / 256;       // 1221
    const int GAT = (N_NODES * 32 + 255) / 256;     // 25000 blocks, warp-per-node

    k_scatter<<<QB + 1, 256>>>(eidx, batch, QB);                              // 0 (+gb)
    k_gather<<<GAT, 256>>>(x);                                                // 1
    k_gemm<true><<<NT, 512, SM_TOTAL>>>(h1, c1w1, c1b1, c1w2, c1b2);          // 2
    k_gather<<<GAT, 256>>>(h1);                                               // 3  (ncu slot)
    k_gemm<false><<<NT, 512, SM_TOTAL>>>(h2, c2w1, c2b1, c2w2, c2b2);         // 4
    k_pool<<<G, 512>>>(h2);                                                   // 5
    k_head<<<G, 128>>>(out, hw0, hb0, hw1, hb1, hw2, hb2, hw3, hb3, hw4, hb4);// 6
}

// round 17
// speedup vs baseline: 1.2438x; 1.2438x over previous
#include <cuda_runtime.h>
#include <cuda_bf16.h>
#include <math.h>
#include <stdint.h>

#define N_NODES 200000
#define N_EDGES 1250000
#define G 128
#define CAP 64
#define NT 782             // ceil(N_NODES / 256)

// ---- dynamic smem byte offsets ----
#define SM_W1H  0
#define SM_W1L  9216
#define SM_W2H  18432
#define SM_W2L  27648
#define SM_AH   36864      // 256 rows x 144 B
#define SM_AL   73728
#define SM_B1   110592
#define SM_B2   110848
#define SM_TOTAL 111104
#define ROWB 144           // padded row stride in bytes (72 halves)

// ---------------- device scratch (zero-initialized at load) ----------------
__device__ int   g_cnt[N_NODES];          // degree cursor; zero at call start
__device__ int   g_esrc[N_NODES * CAP];   // entries >= deg stay 0 (never written)
__device__ float g_h1[N_NODES * 64];
__device__ float g_h2[N_NODES * 64];
__device__ float g_pool[G * 2 * 64];
__device__ int   g_gb[G + 1];

// ---------------- helpers ----------------
__device__ __forceinline__ uint32_t smem_u32(const void* p) {
    uint32_t a;
    asm("{ .reg .u64 t; cvta.to.shared.u64 t, %1; cvt.u32.u64 %0, t; }" : "=r"(a) : "l"(p));
    return a;
}
__device__ __forceinline__ void ldm_x4(uint32_t addr, uint32_t r[4]) {
    asm volatile("ldmatrix.sync.aligned.m8n8.x4.shared.b16 {%0,%1,%2,%3}, [%4];"
                 : "=r"(r[0]), "=r"(r[1]), "=r"(r[2]), "=r"(r[3]) : "r"(addr));
}
__device__ __forceinline__ void ldm_x4t(uint32_t addr, uint32_t r[4]) {
    asm volatile("ldmatrix.sync.aligned.m8n8.x4.trans.shared.b16 {%0,%1,%2,%3}, [%4];"
                 : "=r"(r[0]), "=r"(r[1]), "=r"(r[2]), "=r"(r[3]) : "r"(addr));
}
__device__ __forceinline__ void mma_bf16(float* c, const uint32_t a[4],
                                         uint32_t b0, uint32_t b1) {
    asm volatile("mma.sync.aligned.m16n8k16.row.col.f32.bf16.bf16.f32 "
                 "{%0,%1,%2,%3}, {%4,%5,%6,%7}, {%8,%9}, {%0,%1,%2,%3};"
                 : "+f"(c[0]), "+f"(c[1]), "+f"(c[2]), "+f"(c[3])
                 : "r"(a[0]), "r"(a[1]), "r"(a[2]), "r"(a[3]), "r"(b0), "r"(b1));
}
__device__ __forceinline__ void split_bf16(float v, uint16_t& hi, uint16_t& lo) {
    __nv_bfloat16 h = __float2bfloat16(v);
    float r = v - __bfloat162float(h);
    __nv_bfloat16 l = __float2bfloat16(r);
    hi = __bfloat16_as_ushort(h);
    lo = __bfloat16_as_ushort(l);
}
// packed hi/lo split of a pair: hp = {lo16=bf16(v0), hi16=bf16(v1)}, lp = residuals
__device__ __forceinline__ void split2(float v0, float v1, uint32_t& hp, uint32_t& lp) {
    asm("cvt.rn.bf16x2.f32 %0, %1, %2;" : "=r"(hp) : "f"(v1), "f"(v0));
    float h0 = __uint_as_float(hp << 16);
    float h1 = __uint_as_float(hp & 0xffff0000u);
    float r0 = v0 - h0, r1 = v1 - h1;
    asm("cvt.rn.bf16x2.f32 %0, %1, %2;" : "=r"(lp) : "f"(r1), "f"(r0));
}

// one 64x64 GEMM layer: acc[8][4] = A(16x64, this warp's rows) @ W(64x64)
// 3-term hi/lo: Ah*Wh + Ah*Wl + Al*Wh.
// W fragments via x4.trans: lanes 0-15 -> n-block jp*2, lanes 16-31 -> jp*2+1.
__device__ __forceinline__ void layer64(uint32_t aHi, uint32_t aLo,
                                        uint32_t wHi, uint32_t wLo,
                                        int lane, float acc[8][4]) {
    #pragma unroll
    for (int j = 0; j < 8; j++)
        #pragma unroll
        for (int q = 0; q < 4; q++) acc[j][q] = 0.f;

    uint32_t aOff = (uint32_t)(((lane & 7) + ((lane >> 3) & 1) * 8) * ROWB
                               + ((lane >> 4) * 8) * 2);
    int jhalf = (lane >> 4) & 1;
    #pragma unroll
    for (int kk = 0; kk < 4; kk++) {
        uint32_t ah[4], al[4];
        uint32_t ao = aOff + kk * 32;          // +16 halves per k-step
        ldm_x4(aHi + ao, ah);
        ldm_x4(aLo + ao, al);
        uint32_t brow = kk * 16 + (lane & 15);
        #pragma unroll
        for (int jp = 0; jp < 4; jp++) {
            int jj = jp * 2 + jhalf;
            uint32_t bo = (brow * 72 + jj * 8) * 2;
            uint32_t bh[4], bl[4];
            ldm_x4t(wHi + bo, bh);
            ldm_x4t(wLo + bo, bl);
            mma_bf16(acc[jp * 2],     ah, bh[0], bh[1]);
            mma_bf16(acc[jp * 2],     ah, bl[0], bl[1]);
            mma_bf16(acc[jp * 2],     al, bh[0], bh[1]);
            mma_bf16(acc[jp * 2 + 1], ah, bh[2], bh[3]);
            mma_bf16(acc[jp * 2 + 1], ah, bl[2], bl[3]);
            mma_bf16(acc[jp * 2 + 1], al, bh[2], bh[3]);
        }
    }
}

// ---------------- scatter: bucket edges by dst (4 edges/thread) + gb in last block ----------------
__global__ void k_scatter(const int* __restrict__ e32, const int* __restrict__ b32, int nQB) {
    __shared__ int s_is64;
    if (threadIdx.x == 0) {
        int all0 = 1;
        #pragma unroll 1
        for (int i = 0; i < 64; i++)
            if (e32[2 * i + 1] != 0) { all0 = 0; break; }
        s_is64 = all0;
    }
    __syncthreads();
    if ((int)blockIdx.x == nQB) {
        int g = threadIdx.x;
        if (g > G) return;
        int lo = 0, hi = N_NODES;
        const long long* b64 = (const long long*)b32;
        while (lo < hi) {
            int mid = (lo + hi) >> 1;
            int bv = s_is64 ? (int)b64[mid] : b32[mid];
            if (bv < g) lo = mid + 1; else hi = mid;
        }
        g_gb[g] = lo;
        return;
    }
    int q = blockIdx.x * blockDim.x + threadIdx.x;
    int e0 = q * 4;
    if (e0 >= N_EDGES) return;
    int src[4], dst[4];
    if (s_is64) {
        const longlong2* ps = (const longlong2*)e32;
        const longlong2* pd = (const longlong2*)((const long long*)e32 + N_EDGES);
        longlong2 s01 = __ldg(ps + (e0 >> 1));
        longlong2 s23 = __ldg(ps + (e0 >> 1) + 1);
        longlong2 d01 = __ldg(pd + (e0 >> 1));
        longlong2 d23 = __ldg(pd + (e0 >> 1) + 1);
        src[0] = (int)s01.x; src[1] = (int)s01.y; src[2] = (int)s23.x; src[3] = (int)s23.y;
        dst[0] = (int)d01.x; dst[1] = (int)d01.y; dst[2] = (int)d23.x; dst[3] = (int)d23.y;
    } else {
        int4 s = __ldg((const int4*)e32 + q);
        int4 d = __ldg((const int4*)(e32 + N_EDGES) + q);
        src[0] = s.x; src[1] = s.y; src[2] = s.z; src[3] = s.w;
        dst[0] = d.x; dst[1] = d.y; dst[2] = d.z; dst[3] = d.w;
    }
    #pragma unroll
    for (int j = 0; j < 4; j++) {
        int pos = atomicAdd(&g_cnt[dst[j]], 1);
        if (pos < CAP) g_esrc[((size_t)dst[j] << 6) + pos] = src[j];
    }
}

// ---------------- fused GIN conv (float4 gather: 2 rows per pass) ----------------
template <bool RELU_OUT>
__global__ void __launch_bounds__(512, 2)
k_conv(const float* __restrict__ xin, float* __restrict__ hout,
       const float* __restrict__ w1, const float* __restrict__ b1,
       const float* __restrict__ w2, const float* __restrict__ b2) {
    extern __shared__ char smc[];
    uint32_t sb = smem_u32(smc);
    int t = threadIdx.x, w = t >> 5, lane = t & 31;
    int hl = lane >> 4, l16 = lane & 15;

    // ---- load weights once: split hi/lo into padded [k][n] tiles ----
    for (int idx = t; idx < 4096; idx += 512) {
        int k = idx >> 6, n = idx & 63;
        uint32_t off = (uint32_t)(k * 72 + n) * 2;
        uint16_t hi, lo;
        split_bf16(w1[idx], hi, lo);
        *(uint16_t*)(smc + SM_W1H + off) = hi;
        *(uint16_t*)(smc + SM_W1L + off) = lo;
        split_bf16(w2[idx], hi, lo);
        *(uint16_t*)(smc + SM_W2H + off) = hi;
        *(uint16_t*)(smc + SM_W2L + off) = lo;
    }
    if (t < 64) {
        ((float*)(smc + SM_B1))[t] = b1[t];
        ((float*)(smc + SM_B2))[t] = b2[t];
    }
    __syncthreads();

    const float* b1s = (const float*)(smc + SM_B1);
    const float* b2s = (const float*)(smc + SM_B2);
    const float4* __restrict__ x4 = (const float4*)xin;

    const uint32_t aHiW = sb + SM_AH + (uint32_t)(w * 16 * ROWB);
    const uint32_t aLoW = sb + SM_AL + (uint32_t)(w * 16 * ROWB);
    char* aHiB = smc + SM_AH + w * 16 * ROWB;
    char* aLoB = smc + SM_AL + w * 16 * ROWB;

    int r0 = lane >> 2;
    int cq = (lane & 3) * 2;

    for (int tile = blockIdx.x; tile < NT; tile += gridDim.x) {
        int base = (tile << 8) + w * 16;
        // N_NODES % 16 == 0  =>  this warp has exactly 16 rows or none
        bool active = (base < N_NODES);

        if (active) {
            // all 16 row degrees in one coalesced load
            int degv = (lane < 16) ? g_cnt[base + lane] : 0;
            const int* esb = g_esrc + ((size_t)base << 6);

            // prime row-pair 0: each half-warp loads its node's 64 edge slots
            // (unconditional: slots >= deg are zero-initialized, index 0 is valid)
            int d0 = min(__shfl_sync(0xffffffffu, degv, 0), CAP);
            int d1 = min(__shfl_sync(0xffffffffu, degv, 1), CAP);
            const int* esP = esb + hl * 64;
            int eA = __ldg(esP + l16),      eB = __ldg(esP + 16 + l16);
            int eC = __ldg(esP + 32 + l16), eD = __ldg(esP + 48 + l16);

            #pragma unroll 1
            for (int i = 0; i < 16; i += 2) {
                int cd0 = d0, cd1 = d1;
                int cA = eA, cB = eB, cC = eC, cD = eD;
                if (i + 2 < 16) {   // prefetch next pair's edge lists
                    d0 = min(__shfl_sync(0xffffffffu, degv, i + 2), CAP);
                    d1 = min(__shfl_sync(0xffffffffu, degv, i + 3), CAP);
                    const int* esN = esb + ((i + 2 + hl) << 6);
                    eA = __ldg(esN + l16);      eB = __ldg(esN + 16 + l16);
                    eC = __ldg(esN + 32 + l16); eD = __ldg(esN + 48 + l16);
                }
                int myDeg = hl ? cd1 : cd0;
                int mx = cd0 > cd1 ? cd0 : cd1;
                int row = i + hl;                     // this half-warp's row
                float4 a = __ldg(&x4[(size_t)(base + row) * 16 + l16]);

                #pragma unroll 1
                for (int e = 0; e < mx; e += 4) {
                    float4 v[4];
                    #pragma unroll
                    for (int k = 0; k < 4; k++) {
                        int idx = e + k;
                        int reg = idx < 16 ? cA : idx < 32 ? cB : idx < 48 ? cC : cD;
                        int s = __shfl_sync(0xffffffffu, reg, idx & 15, 16);
                        v[k] = __ldg(&x4[(size_t)s * 16 + l16]);
                    }
                    #pragma unroll
                    for (int k = 0; k < 4; k++) {
                        if (e + k < myDeg) {
                            a.x += v[k].x; a.y += v[k].y;
                            a.z += v[k].z; a.w += v[k].w;
                        }
                    }
                }
                uint32_t hp0, lp0, hp1, lp1;
                split2(a.x, a.y, hp0, lp0);
                split2(a.z, a.w, hp1, lp1);
                *(uint2*)(aHiB + row * ROWB + l16 * 8) = make_uint2(hp0, hp1);
                *(uint2*)(aLoB + row * ROWB + l16 * 8) = make_uint2(lp0, lp1);
            }
        }
        __syncwarp();

        // ---- layer 1 ----
        float acc[8][4];
        layer64(aHiW, aLoW, sb + SM_W1H, sb + SM_W1L, lane, acc);

        // epilogue 1: bias + relu, split back into own A rows
        #pragma unroll
        for (int j = 0; j < 8; j++) {
            int cb = j * 8 + cq;
            float v0 = fmaxf(acc[j][0] + b1s[cb],     0.f);
            float v1 = fmaxf(acc[j][1] + b1s[cb + 1], 0.f);
            float v2 = fmaxf(acc[j][2] + b1s[cb],     0.f);
            float v3 = fmaxf(acc[j][3] + b1s[cb + 1], 0.f);
            uint32_t hp0, lp0, hp1, lp1;
            split2(v0, v1, hp0, lp0);
            split2(v2, v3, hp1, lp1);
            *(uint32_t*)(aHiB + r0 * ROWB + cb * 2)       = hp0;
            *(uint32_t*)(aLoB + r0 * ROWB + cb * 2)       = lp0;
            *(uint32_t*)(aHiB + (r0 + 8) * ROWB + cb * 2) = hp1;
            *(uint32_t*)(aLoB + (r0 + 8) * ROWB + cb * 2) = lp1;
        }
        __syncwarp();

        // ---- layer 2 ----
        layer64(aHiW, aLoW, sb + SM_W2H, sb + SM_W2L, lane, acc);

        // epilogue 2: bias (+relu) -> gmem f32
        if (active) {
            int n0 = base + r0;
            int n1 = n0 + 8;
            #pragma unroll
            for (int j = 0; j < 8; j++) {
                int cb = j * 8 + cq;
                float v0 = acc[j][0] + b2s[cb];
                float v1 = acc[j][1] + b2s[cb + 1];
                float v2 = acc[j][2] + b2s[cb];
                float v3 = acc[j][3] + b2s[cb + 1];
                if (RELU_OUT) {
                    v0 = fmaxf(v0, 0.f); v1 = fmaxf(v1, 0.f);
                    v2 = fmaxf(v2, 0.f); v3 = fmaxf(v3, 0.f);
                }
                *(float2*)(hout + (size_t)n0 * 64 + cb) = make_float2(v0, v1);
                *(float2*)(hout + (size_t)n1 * 64 + cb) = make_float2(v2, v3);
            }
        }
        __syncwarp();
    }
}

// ---------------- pooling (+ re-zero g_cnt) ----------------
__global__ void __launch_bounds__(512) k_pool(const float* __restrict__ h) {
    for (int i = blockIdx.x * blockDim.x + threadIdx.x; i < N_NODES;
         i += gridDim.x * blockDim.x)
        g_cnt[i] = 0;

    __shared__ float ssum[8][64], smax[8][64];
    int g = blockIdx.x, t = threadIdx.x;
    int col = t & 63, ch = t >> 6;
    int beg = g_gb[g], end = g_gb[g + 1];
    float s = 0.f, m = -INFINITY;
    for (int i = beg + ch; i < end; i += 8) {
        float v = h[i * 64 + col];
        s += v; m = fmaxf(m, v);
    }
    ssum[ch][col] = s; smax[ch][col] = m;
    __syncthreads();
    if (t < 64) {
        float S = 0.f, M = -INFINITY;
        #pragma unroll
        for (int c = 0; c < 8; c++) { S += ssum[c][t]; M = fmaxf(M, smax[c][t]); }
        g_pool[g * 128 + t]      = S;
        g_pool[g * 128 + 64 + t] = M;
    }
}

// ---------------- head MLP ----------------
__device__ __forceinline__ float silu(float x) { return x / (1.f + expf(-x)); }

__global__ void __launch_bounds__(128) k_head(float* __restrict__ out,
        const float* __restrict__ w0, const float* __restrict__ b0,
        const float* __restrict__ w1, const float* __restrict__ b1,
        const float* __restrict__ w2, const float* __restrict__ b2,
        const float* __restrict__ w3, const float* __restrict__ b3,
        const float* __restrict__ w4, const float* __restrict__ b4) {
    __shared__ float bufA[128], bufB[128];
    int g = blockIdx.x, t = threadIdx.x;
    bufA[t] = g_pool[g * 128 + t];
    __syncthreads();
    {
        float a = b0[t];
        #pragma unroll 8
        for (int k = 0; k < 128; k++) a = fmaf(bufA[k], w0[k * 128 + t], a);
        bufB[t] = silu(a);
    }
    __syncthreads();
    if (t < 64) {
        float a = b1[t];
        #pragma unroll 8
        for (int k = 0; k < 128; k++) a = fmaf(bufB[k], w1[k * 64 + t], a);
        bufA[t] = silu(a);
    }
    __syncthreads();
    if (t < 32) {
        float a = b2[t];
        #pragma unroll 8
        for (int k = 0; k < 64; k++) a = fmaf(bufA[k], w2[k * 32 + t], a);
        bufB[t] = silu(a);
    }
    __syncthreads();
    if (t < 16) {
        float a = b3[t];
        #pragma unroll
        for (int k = 0; k < 32; k++) a = fmaf(bufB[k], w3[k * 16 + t], a);
        bufA[t] = silu(a);
    }
    __syncthreads();
    if (t == 0) {
        float a = b4[0];
        #pragma unroll
        for (int k = 0; k < 16; k++) a = fmaf(bufA[k], w4[k], a);
        out[g] = a;
    }
}

// ---------------- launch ----------------
extern "C" void kernel_launch(void* const* d_in, const int* in_sizes, int n_in,
                              void* d_out, int out_size) {
    const float* x     = (const float*)d_in[0];
    const int*   eidx  = (const int*)d_in[1];
    const int*   batch = (const int*)d_in[2];
    const float* c1w1 = (const float*)d_in[3];
    const float* c1b1 = (const float*)d_in[4];
    const float* c1w2 = (const float*)d_in[5];
    const float* c1b2 = (const float*)d_in[6];
    const float* c2w1 = (const float*)d_in[7];
    const float* c2b1 = (const float*)d_in[8];
    const float* c2w2 = (const float*)d_in[9];
    const float* c2b2 = (const float*)d_in[10];
    const float* hw0 = (const float*)d_in[11];
    const float* hb0 = (const float*)d_in[12];
    const float* hw1 = (const float*)d_in[13];
    const float* hb1 = (const float*)d_in[14];
    const float* hw2 = (const float*)d_in[15];
    const float* hb2 = (const float*)d_in[16];
    const float* hw3 = (const float*)d_in[17];
    const float* hb3 = (const float*)d_in[18];
    const float* hw4 = (const float*)d_in[19];
    const float* hb4 = (const float*)d_in[20];
    float* out = (float*)d_out;

    void *p1, *p2;
    cudaGetSymbolAddress(&p1, g_h1);
    cudaGetSymbolAddress(&p2, g_h2);
    float* h1 = (float*)p1;
    float* h2 = (float*)p2;

    static int attrDone = 0;
    if (!attrDone) {
        cudaFuncSetAttribute(k_conv<true>,  cudaFuncAttributeMaxDynamicSharedMemorySize, SM_TOTAL);
        cudaFuncSetAttribute(k_conv<false>, cudaFuncAttributeMaxDynamicSharedMemorySize, SM_TOTAL);
        attrDone = 1;
    }

    const int QB = (N_EDGES / 4 + 255) / 256;   // 1221 (N_EDGES % 4 == 0)
    const int convGrid = 296;                   // 2 CTAs/SM, grid-stride over 782 tiles

    k_scatter<<<QB + 1, 256>>>(eidx, batch, QB);                                // 0 (+gb)
    k_conv<true><<<convGrid, 512, SM_TOTAL>>>(x, h1, c1w1, c1b1, c1w2, c1b2);   // 1
    k_conv<false><<<convGrid, 512, SM_TOTAL>>>(h1, h2, c2w1, c2b1, c2w2, c2b2); // 2
    k_pool<<<G, 512>>>(h2);                                                     // 3
    k_head<<<G, 128>>>(out, hw0, hb0, hw1, hb1, hw2, hb2, hw3, hb3, hw4, hb4);  // 4
}